// round 4
// baseline (speedup 1.0000x reference)
#include <cuda_runtime.h>

// PaillerMLP: out = W3 @ ((W2 @ ((W1 @ x + b1)^2) + b2)^2) + b3
// D_IN=4096, D_HID=8192, D_OUT=1000, all fp32.
// HBM-bound matvec chain: ~415 MiB weight traffic -> ~52 us floor at 8 TB/s.

#define D_IN  4096
#define D_HID 8192
#define D_OUT 1000

// Intermediate activations (scratch via __device__ globals — no allocs allowed).
__device__ float g_h1[D_HID];
__device__ float g_h2[D_HID];

// Warp-per-row matvec. 256 threads = 8 warps = 8 rows per block.
// x staged in shared once per block (amortized over 8 rows) so the LTS path
// carries ~1.125x the W traffic instead of 2x.
template <int K, bool SQUARE>
__global__ __launch_bounds__(256, 1)
void matvec_kernel(const float* __restrict__ W,
                   const float* __restrict__ x,
                   const float* __restrict__ b,
                   float* __restrict__ out,
                   int M)
{
    __shared__ float sx[K];

    const int tid = threadIdx.x;

    // Cooperative float4 staging of x into shared.
    const float4* x4  = reinterpret_cast<const float4*>(x);
    float4*       sx4 = reinterpret_cast<float4*>(sx);
    #pragma unroll
    for (int i = tid; i < K / 4; i += 256) {
        sx4[i] = x4[i];
    }
    __syncthreads();

    const int wid  = tid >> 5;
    const int lane = tid & 31;
    const int row  = blockIdx.x * 8 + wid;
    if (row >= M) return;

    const float4* W4 = reinterpret_cast<const float4*>(W + (size_t)row * K);

    float acc = 0.0f;
    // K/4 float4 per row, strided by 32 lanes. unroll 8 -> 8 independent
    // LDG.128 in flight per lane before the FMA chain consumes them.
    #pragma unroll 8
    for (int i = lane; i < K / 4; i += 32) {
        float4 w  = W4[i];
        float4 xv = sx4[i];
        acc += w.x * xv.x + w.y * xv.y + w.z * xv.z + w.w * xv.w;
    }

    // Warp reduction.
    #pragma unroll
    for (int off = 16; off; off >>= 1)
        acc += __shfl_xor_sync(0xffffffffu, acc, off);

    if (lane == 0) {
        float v = acc + b[row];
        if (SQUARE) v = v * v;
        out[row] = v;
    }
}

extern "C" void kernel_launch(void* const* d_in, const int* in_sizes, int n_in,
                              void* d_out, int out_size)
{
    const float* x  = (const float*)d_in[0];
    const float* W1 = (const float*)d_in[1];
    const float* b1 = (const float*)d_in[2];
    const float* W2 = (const float*)d_in[3];
    const float* b2 = (const float*)d_in[4];
    const float* W3 = (const float*)d_in[5];
    const float* b3 = (const float*)d_in[6];
    float* out = (float*)d_out;

    // Symbol address lookups are not stream ops — safe under graph capture.
    float* h1 = nullptr;
    float* h2 = nullptr;
    cudaGetSymbolAddress((void**)&h1, g_h1);
    cudaGetSymbolAddress((void**)&h2, g_h2);

    // Layer 1: h1 = (W1 @ x + b1)^2   [8192 x 4096]
    matvec_kernel<D_IN, true><<<D_HID / 8, 256>>>(W1, x, b1, h1, D_HID);

    // Layer 2: h2 = (W2 @ h1 + b2)^2  [8192 x 8192]
    matvec_kernel<D_HID, true><<<D_HID / 8, 256>>>(W2, h1, b2, h2, D_HID);

    // Layer 3: out = W3 @ h2 + b3     [1000 x 8192]
    matvec_kernel<D_HID, false><<<(D_OUT + 7) / 8, 256>>>(W3, h2, b3, out, D_OUT);
}

// round 6
// speedup vs baseline: 1.0033x; 1.0033x over previous
#include <cuda_runtime.h>

// PaillerMLP: out = W3 @ ((W2 @ ((W1 @ x + b1)^2) + b2)^2) + b3
// D_IN=4096, D_HID=8192, D_OUT=1000, all fp32.
// HBM-bound matvec chain: ~415 MiB weight traffic.
// R4: 78.6us @ DRAM 69%, occ 35% (reg-limited, 3 blocks/SM).
// R5: force 4 blocks/SM, front-batch 8x LDG.128 streaming (__ldcs),
//     dual accumulators to break the FFMA dependency chain.

#define D_IN  4096
#define D_HID 8192
#define D_OUT 1000

// Intermediate activations (scratch via __device__ globals — no allocs allowed).
__device__ float g_h1[D_HID];
__device__ float g_h2[D_HID];

// Warp-per-row matvec. 256 threads = 8 warps = 8 rows per block.
// x staged in shared once per block (amortized over 8 rows).
// __launch_bounds__(256, 4): cap at 64 regs -> 4 blocks/SM -> 32 warps (50% occ).
template <int K, bool SQUARE>
__global__ __launch_bounds__(256, 4)
void matvec_kernel(const float* __restrict__ W,
                   const float* __restrict__ x,
                   const float* __restrict__ b,
                   float* __restrict__ out,
                   int M)
{
    __shared__ float sx[K];

    const int tid = threadIdx.x;

    // Cooperative float4 staging of x into shared.
    const float4* x4  = reinterpret_cast<const float4*>(x);
    float4*       sx4 = reinterpret_cast<float4*>(sx);
    #pragma unroll
    for (int i = tid; i < K / 4; i += 256) {
        sx4[i] = x4[i];
    }
    __syncthreads();

    const int wid  = tid >> 5;
    const int lane = tid & 31;
    const int row  = blockIdx.x * 8 + wid;
    if (row >= M) return;

    const float4* W4 = reinterpret_cast<const float4*>(W + (size_t)row * K);

    constexpr int ITERS = K / 4 / 32;   // float4's per lane (32 or 64)

    float acc0 = 0.0f, acc1 = 0.0f;

    // Outer loop not unrolled; inner chunk front-batches 8 streaming LDG.128
    // (MLP_p1 = 8 per warp) before consuming them, with the FMA work split
    // across two accumulators so the dependency chain is 16 deep, not 32.
    #pragma unroll 1
    for (int base = 0; base < ITERS; base += 8) {
        float4 w[8];
        #pragma unroll
        for (int u = 0; u < 8; u++) {
            // evict-first streaming load: W is touched exactly once
            w[u] = __ldcs(&W4[(base + u) * 32 + lane]);
        }
        #pragma unroll
        for (int u = 0; u < 8; u++) {
            const float4 xv = sx4[(base + u) * 32 + lane];
            if (u & 1) {
                acc1 += w[u].x * xv.x + w[u].y * xv.y
                      + w[u].z * xv.z + w[u].w * xv.w;
            } else {
                acc0 += w[u].x * xv.x + w[u].y * xv.y
                      + w[u].z * xv.z + w[u].w * xv.w;
            }
        }
    }

    float acc = acc0 + acc1;

    // Warp reduction.
    #pragma unroll
    for (int off = 16; off; off >>= 1)
        acc += __shfl_xor_sync(0xffffffffu, acc, off);

    if (lane == 0) {
        float v = acc + b[row];
        if (SQUARE) v = v * v;
        out[row] = v;
    }
}

extern "C" void kernel_launch(void* const* d_in, const int* in_sizes, int n_in,
                              void* d_out, int out_size)
{
    const float* x  = (const float*)d_in[0];
    const float* W1 = (const float*)d_in[1];
    const float* b1 = (const float*)d_in[2];
    const float* W2 = (const float*)d_in[3];
    const float* b2 = (const float*)d_in[4];
    const float* W3 = (const float*)d_in[5];
    const float* b3 = (const float*)d_in[6];
    float* out = (float*)d_out;

    float* h1 = nullptr;
    float* h2 = nullptr;
    cudaGetSymbolAddress((void**)&h1, g_h1);
    cudaGetSymbolAddress((void**)&h2, g_h2);

    // Layer 1: h1 = (W1 @ x + b1)^2   [8192 x 4096]
    matvec_kernel<D_IN, true><<<D_HID / 8, 256>>>(W1, x, b1, h1, D_HID);

    // Layer 2: h2 = (W2 @ h1 + b2)^2  [8192 x 8192]
    matvec_kernel<D_HID, true><<<D_HID / 8, 256>>>(W2, h1, b2, h2, D_HID);

    // Layer 3: out = W3 @ h2 + b3     [1000 x 8192]
    matvec_kernel<D_HID, false><<<(D_OUT + 7) / 8, 256>>>(W3, h2, b3, out, D_OUT);
}